// round 12
// baseline (speedup 1.0000x reference)
#include <cuda_runtime.h>
#include <stdint.h>

// Problem constants
#define HW        512
#define IMG_PIX   (HW * HW)            // 262144
#define B_IMG     64
#define IMG_ELEMS (B_IMG * IMG_PIX)    // 16777216 floats (image output part)
#define NPERM     4096
#define NELEM     4096
#define NSAMP     250
#define NBIN      512
#define SCATN     3072                 // flagged-element scratch (mean ~1620)
#define TCAND     64u                  // Phase-A candidate digit threshold
#define CAPA      1024u                // Phase-A candidate capacity (mean 512)

// Dynamic smem layout (bytes)
#define OFF_ARR     0                        // 4096*8 (B composites; A reuses)
#define OFF_SCAT    32768                    // 3072*8
#define OFF_HIST    (OFF_SCAT + SCATN*8)     // 512*4
#define OFF_STARTS  (OFF_HIST + 2048)        // 513*4
#define OFF_FST     (OFF_STARTS + 2052)      // 512*4
#define OFF_WSUM    (OFF_FST + 2048)         // 16*4
#define OFF_CNT     (OFF_WSUM + 64)          // 2*4  (ncand, totalScat)
#define OFF_FIDX    (OFF_CNT + 8)            // 250*4
#define OFF_POSMAP  (OFF_FIDX + 1000)        // 4096*2
#define OFF_BITMAP  (OFF_POSMAP + 8192)      // 128*4
#define OFF_FLAG    (OFF_BITMAP + 512)       // 512
#define SMEM_BYTES  (OFF_FLAG + 512)         // ~74 KB -> 3 CTAs/SM

// ---------------------------------------------------------------------------
#define H0 0.3535533905932738f
#define H1 0.4903926402016152f
#define H2 0.4619397662556434f
#define H3 0.4157348061512726f
#define H4 0.3535533905932738f
#define H5 0.2777851165098011f
#define H6 0.1913417161825449f
#define H7 0.0975451610080641f

__constant__ float Qc[8][8] = {
    { H0,  H0,  H0,  H0,  H0,  H0,  H0,  H0},
    { H1,  H3,  H5,  H7, -H7, -H5, -H3, -H1},
    { H2,  H6, -H6, -H2, -H2, -H6,  H6,  H2},
    { H3, -H7, -H1, -H5,  H5,  H1,  H7, -H3},
    { H4, -H4, -H4,  H4,  H4, -H4, -H4,  H4},
    { H5, -H1,  H7,  H3, -H3, -H7,  H1, -H5},
    { H6, -H2,  H2, -H6, -H6,  H2, -H2,  H6},
    { H7, -H5,  H3, -H1,  H1, -H3,  H5, -H7},
};

__constant__ int ZIGc[64] = {
     0,  1,  8, 16,  9,  2,  3, 10, 17, 24, 32, 25, 18, 11,  4,  5,
    12, 19, 26, 33, 40, 48, 41, 34, 27, 20, 13,  6,  7, 14, 21, 28,
    35, 42, 49, 56, 57, 50, 43, 36, 29, 22, 15, 23, 30, 37, 44, 51,
    58, 59, 52, 45, 38, 31, 39, 46, 53, 60, 61, 54, 47, 55, 62, 63
};

// ---------------------------------------------------------------------------
// Threefry-2x32 (20 rounds) — matches JAX exactly (verified bit-exact)
// ---------------------------------------------------------------------------
__device__ __forceinline__ void tf2(uint32_t k0, uint32_t k1,
                                    uint32_t& x0, uint32_t& x1) {
    const uint32_t ks2 = k0 ^ k1 ^ 0x1BD11BDAu;
    x0 += k0; x1 += k1;
#define TFR(r) { x0 += x1; x1 = (x1 << (r)) | (x1 >> (32 - (r))); x1 ^= x0; }
    TFR(13) TFR(15) TFR(26) TFR(6)   x0 += k1;  x1 += ks2 + 1u;
    TFR(17) TFR(29) TFR(16) TFR(24)  x0 += ks2; x1 += k0  + 2u;
    TFR(13) TFR(15) TFR(26) TFR(6)   x0 += k0;  x1 += k1  + 3u;
    TFR(17) TFR(29) TFR(16) TFR(24)  x0 += k1;  x1 += ks2 + 4u;
    TFR(13) TFR(15) TFR(26) TFR(6)   x0 += ks2; x1 += k0  + 5u;
#undef TFR
}

// ---------------------------------------------------------------------------
// Kernel 1: RGB->Y + 8x8 2D DCT. One thread = one 8x8 block. (48us, 63% DRAM)
// ---------------------------------------------------------------------------
__global__ void __launch_bounds__(256) dct_kernel(const float* __restrict__ x,
                                                  float* __restrict__ out) {
    int g   = blockIdx.x * 256 + threadIdx.x;
    int b   = g >> 12;
    int blk = g & 4095;
    int bi  = blk >> 6;
    int bj  = blk & 63;

    const float* xr = x + (size_t)b * 3 * IMG_PIX;
    const float* xg = xr + IMG_PIX;
    const float* xb = xg + IMG_PIX;
    int base = bi * 8 * HW + bj * 8;

    float T[8][8];
#pragma unroll
    for (int i = 0; i < 8; i++)
#pragma unroll
        for (int jj = 0; jj < 8; jj++) T[i][jj] = 0.0f;

#pragma unroll
    for (int k = 0; k < 8; k++) {
        int off = base + k * HW;
        float4 r0 = __ldg((const float4*)(xr + off));
        float4 r1 = __ldg((const float4*)(xr + off) + 1);
        float4 g0 = __ldg((const float4*)(xg + off));
        float4 g1 = __ldg((const float4*)(xg + off) + 1);
        float4 c0 = __ldg((const float4*)(xb + off));
        float4 c1 = __ldg((const float4*)(xb + off) + 1);

        float y[8];
        y[0] = 0.299f * r0.x + 0.587f * g0.x + 0.114f * c0.x;
        y[1] = 0.299f * r0.y + 0.587f * g0.y + 0.114f * c0.y;
        y[2] = 0.299f * r0.z + 0.587f * g0.z + 0.114f * c0.z;
        y[3] = 0.299f * r0.w + 0.587f * g0.w + 0.114f * c0.w;
        y[4] = 0.299f * r1.x + 0.587f * g1.x + 0.114f * c1.x;
        y[5] = 0.299f * r1.y + 0.587f * g1.y + 0.114f * c1.y;
        y[6] = 0.299f * r1.z + 0.587f * g1.z + 0.114f * c1.z;
        y[7] = 0.299f * r1.w + 0.587f * g1.w + 0.114f * c1.w;

#pragma unroll
        for (int i = 0; i < 8; i++) {
            float q = Qc[i][k];
#pragma unroll
            for (int jj = 0; jj < 8; jj++)
                T[i][jj] = fmaf(q, y[jj], T[i][jj]);
        }
    }

    float* o = out + (size_t)b * IMG_PIX + base;
#pragma unroll
    for (int i = 0; i < 8; i++) {
        float d[8];
#pragma unroll
        for (int l = 0; l < 8; l++) {
            float acc = 0.0f;
#pragma unroll
            for (int k = 0; k < 8; k++)
                acc = fmaf(T[i][k], Qc[l][k], acc);
            d[l] = acc;
        }
        float4* op = (float4*)(o + i * HW);
        op[0] = make_float4(d[0], d[1], d[2], d[3]);
        op[1] = make_float4(d[4], d[5], d[6], d[7]);
    }
}

// exclusive 512-bin scan; all 512 threads must participate (contains syncs)
__device__ __forceinline__ uint32_t scan512(uint32_t h, int lane, int wid,
                                            uint32_t* wsum) {
    uint32_t inc = h;
#pragma unroll
    for (int off = 1; off < 32; off <<= 1) {
        uint32_t nn = __shfl_up_sync(0xFFFFFFFFu, inc, off);
        if (lane >= off) inc += nn;
    }
    if (lane == 31) wsum[wid] = inc;
    __syncthreads();
    if (wid == 0) {
        uint32_t v = (lane < 16) ? wsum[lane] : 0u;
        uint32_t vi = v;
#pragma unroll
        for (int off = 1; off < 16; off <<= 1) {
            uint32_t nn = __shfl_up_sync(0xFFFFFFFFu, vi, off);
            if (lane >= off) vi += nn;
        }
        if (lane < 16) wsum[lane] = vi - v;
    }
    __syncthreads();
    return inc - h + wsum[wid];
}

// ---------------------------------------------------------------------------
// Kernel 2: JAX permutation + fused gather.
//  Phase A: round-2 top-250 via THRESHOLD selection (digit < TCAND candidates
//           only; downward-closed => candidate rank == global rank).
//           posmap[round1_rank]=pos, bitmap of selected ranks.
//  Phase B: round-1 sparse sort — full histogram, bitmap-flagged buckets,
//           compacted scatter, rank over compacted list; winners emit index.
// Composite: (sk << 12) | i  (44-bit, distinct). Digit = bits [35,44).
// ---------------------------------------------------------------------------
__global__ void __launch_bounds__(512, 3) perm_kernel(float* __restrict__ out) {
    extern __shared__ char smem[];
    unsigned long long* arr  = (unsigned long long*)(smem + OFF_ARR);
    unsigned long long* cand = arr;                            // A: [0,1024)
    unsigned long long* scatA = arr + 1024;                    // A: grouped
    unsigned long long* scat = (unsigned long long*)(smem + OFF_SCAT);
    uint32_t* hist   = (uint32_t*)(smem + OFF_HIST);           // + cursor
    uint32_t* starts = (uint32_t*)(smem + OFF_STARTS);
    uint32_t* fst    = (uint32_t*)(smem + OFF_FST);
    uint32_t* wsum   = (uint32_t*)(smem + OFF_WSUM);
    uint32_t* cnt    = (uint32_t*)(smem + OFF_CNT);            // [0]=ncand [1]=nscat
    int*      fidx   = (int*)(smem + OFF_FIDX);
    uint16_t* posmap = (uint16_t*)(smem + OFF_POSMAP);
    uint32_t* bitmap = (uint32_t*)(smem + OFF_BITMAP);
    uint8_t*  flag   = (uint8_t*)(smem + OFF_FLAG);

    const int tid  = threadIdx.x;
    const int lane = tid & 31;
    const int wid  = tid >> 5;
    const int j    = blockIdx.x;

    // keys[j] from top-level split of key(0) = (0,0)
    uint32_t key0 = 0u, key1 = (uint32_t)j;
    tf2(0u, 0u, key0, key1);
    // subkeys: round1 = tf2(key,(0,1)); key2 = tf2(key,(0,0)); round2 = tf2(key2,(0,1))
    uint32_t s0 = 0u, s1 = 1u; tf2(key0, key1, s0, s1);
    uint32_t k20 = 0u, k21 = 0u; tf2(key0, key1, k20, k21);
    uint32_t t0 = 0u, t1 = 1u; tf2(k20, k21, t0, t1);

    // =============== PHASE A: round-2 top-250 (threshold) ==================
    hist[tid] = 0;
    if (tid < 128) bitmap[tid] = 0;
    if (tid == 0) { cnt[0] = 0; cnt[1] = 0; }
    {   // posmap := 0xFFFF
        uint32_t* pm = (uint32_t*)posmap;
        pm[tid] = 0xFFFFFFFFu; pm[tid + 512] = 0xFFFFFFFFu;
        pm[tid + 1024] = 0xFFFFFFFFu; pm[tid + 1536] = 0xFFFFFFFFu;
    }
    __syncthreads();

    for (int q = 0; q < 8; q++) {
        int i = tid + q * 512;
        uint32_t b1 = 0u, b2 = (uint32_t)i;
        tf2(t0, t1, b1, b2);
        uint32_t sk = b1 ^ b2;
        uint32_t d = sk >> 23;
        if (d < TCAND) {
            unsigned long long cc =
                ((unsigned long long)sk << 12) | (unsigned)i;
            uint32_t p = atomicAdd(&cnt[0], 1u);
            if (p < CAPA) cand[p] = cc;
            atomicAdd(&hist[d], 1u);
        }
    }
    __syncthreads();

    {   // scan (bins >= TCAND are zero)
        uint32_t h = hist[tid];
        uint32_t excl = scan512(h, lane, wid, wsum);
        starts[tid] = excl;
        hist[tid]   = excl;      // cursor
    }
    __syncthreads();

    const uint32_t NC = min(cnt[0], CAPA);
    // group candidates by digit
    for (uint32_t t = tid; t < NC; t += 512) {
        unsigned long long cc = cand[t];
        uint32_t d = (uint32_t)(cc >> 35);
        uint32_t p = atomicAdd(&hist[d], 1u);
        scatA[p] = cc;
    }
    __syncthreads();

    // rank candidates; winners: posmap + bitmap
    for (uint32_t t = tid; t < NC; t += 512) {
        unsigned long long cc = scatA[t];
        uint32_t d = (uint32_t)(cc >> 35);
        uint32_t lo = starts[d], hi = starts[d + 1];
        uint32_t r = 0;
        for (uint32_t m = lo; m < hi; m++)
            r += (scatA[m] < cc);
        uint32_t pos = lo + r;
        if (pos < NSAMP) {
            uint32_t slot = (uint32_t)(cc & 0xFFFull);
            posmap[slot] = (uint16_t)pos;
            atomicOr(&bitmap[slot >> 5], 1u << (slot & 31));
        }
    }
    __syncthreads();
    hist[tid] = 0;
    __syncthreads();

    // ==================== PHASE B: round-1 sparse sort ======================
    for (int q = 0; q < 8; q++) {
        int i = tid + q * 512;
        uint32_t b1 = 0u, b2 = (uint32_t)i;
        tf2(s0, s1, b1, b2);
        unsigned long long cc =
            ((unsigned long long)(b1 ^ b2) << 12) | (unsigned)i;
        arr[i] = cc;
        atomicAdd(&hist[(uint32_t)(cc >> 35)], 1u);
    }
    __syncthreads();

    uint32_t hB = hist[tid];
    {
        uint32_t excl = scan512(hB, lane, wid, wsum);
        starts[tid] = excl;
        if (tid == 0) starts[NBIN] = NELEM;
    }
    __syncthreads();

    // flag buckets via bitmap over rank range [lo, hi)
    uint8_t fl = 0;
    {
        uint32_t lo = starts[tid], hi = starts[tid + 1];
        if (hi > lo) {
            uint32_t w0 = lo >> 5, w1 = (hi - 1) >> 5;
            uint32_t f = 0;
            for (uint32_t w = w0; w <= w1; w++) {
                uint32_t m = 0xFFFFFFFFu;
                if (w == w0) m &= 0xFFFFFFFFu << (lo & 31);
                if (w == w1) m &= 0xFFFFFFFFu >> (31 - ((hi - 1) & 31));
                f |= bitmap[w] & m;
            }
            fl = (f != 0);
        }
        flag[tid] = fl;
    }
    __syncthreads();

    // compacted scan over flagged buckets
    {
        uint32_t fh = fl ? hB : 0u;
        uint32_t fexcl = scan512(fh, lane, wid, wsum);
        fst[tid]  = fexcl;
        hist[tid] = fexcl;       // cursor
        if (tid == 511) cnt[1] = fexcl + fh;
    }
    __syncthreads();

    // scatter flagged-bucket elements (compacted)
    for (int q = 0; q < 8; q++) {
        unsigned long long cc = arr[tid + q * 512];
        uint32_t d = (uint32_t)(cc >> 35);
        if (flag[d]) {
            uint32_t p = atomicAdd(&hist[d], 1u);
            if (p < SCATN) scat[p] = cc;
        }
    }
    __syncthreads();

    // rank compacted elements; winners emit block index
    const uint32_t NS = min(cnt[1], (uint32_t)SCATN);
    for (uint32_t t = tid; t < NS; t += 512) {
        unsigned long long cc = scat[t];
        uint32_t d = (uint32_t)(cc >> 35);
        uint32_t flo = fst[d];
        uint32_t bsz = starts[d + 1] - starts[d];
        uint32_t r = 0;
        for (uint32_t m = flo; m < flo + bsz; m++)
            r += (scat[m] < cc);
        uint32_t fp = starts[d] + r;          // global round-1 rank
        uint16_t p = posmap[fp];
        if (p != 0xFFFFu)
            fidx[p] = (int)(cc & 0xFFFull);
    }
    __syncthreads();

    // ========================= fused sample gather =========================
    if (tid < NSAMP) {
        int b = j >> 6;
        int z = j & 63;
        int blk = fidx[tid];
        int loc = ZIGc[z];
        int u = loc >> 3, v = loc & 7;
        int bi = blk >> 6, bj = blk & 63;
        float val = out[(size_t)b * IMG_PIX +
                        (size_t)(bi * 8 + u) * HW + bj * 8 + v];
        out[(size_t)IMG_ELEMS + (size_t)j * NSAMP + tid] = val;
    }
}

// ---------------------------------------------------------------------------
extern "C" void kernel_launch(void* const* d_in, const int* in_sizes, int n_in,
                              void* d_out, int out_size) {
    (void)in_sizes; (void)n_in; (void)out_size;
    const float* x = (const float*)d_in[0];
    float* out = (float*)d_out;

    cudaFuncSetAttribute(perm_kernel,
                         cudaFuncAttributeMaxDynamicSharedMemorySize,
                         SMEM_BYTES);

    dct_kernel<<<1024, 256>>>(x, out);
    perm_kernel<<<NPERM, 512, SMEM_BYTES>>>(out);
}

// round 13
// speedup vs baseline: 1.0461x; 1.0461x over previous
#include <cuda_runtime.h>
#include <stdint.h>

// Problem constants
#define HW        512
#define IMG_PIX   (HW * HW)            // 262144
#define B_IMG     64
#define IMG_ELEMS (B_IMG * IMG_PIX)    // 16777216 floats (image output part)
#define NPERM     4096
#define NELEM     4096
#define NSAMP     250
#define NBIN      512
#define SCATN     3072                 // flagged-element scratch (mean ~1620)
#define TCAND     64u                  // Phase-A candidate digit threshold
#define CAPA      1024u                // Phase-A candidate capacity (mean 512)

// Dynamic smem layout (bytes)
#define OFF_ARR     0                        // 4096*8 (B composites; A reuses)
#define OFF_SCAT    32768                    // 3072*8
#define OFF_HIST    (OFF_SCAT + SCATN*8)     // 512*4
#define OFF_STARTS  (OFF_HIST + 2048)        // 513*4
#define OFF_FST     (OFF_STARTS + 2052)      // 512*4
#define OFF_WSUM    (OFF_FST + 2048)         // 16*4
#define OFF_CNT     (OFF_WSUM + 64)          // 2*4  (ncand, totalScat)
#define OFF_FIDX    (OFF_CNT + 8)            // 250*4
#define OFF_POSMAP  (OFF_FIDX + 1000)        // 4096*2
#define OFF_BITMAP  (OFF_POSMAP + 8192)      // 128*4
#define OFF_FLAG    (OFF_BITMAP + 512)       // 512
#define SMEM_BYTES  (OFF_FLAG + 512)         // ~74 KB -> 3 CTAs/SM

// ---------------------------------------------------------------------------
#define H0 0.3535533905932738f
#define H1 0.4903926402016152f
#define H2 0.4619397662556434f
#define H3 0.4157348061512726f
#define H4 0.3535533905932738f
#define H5 0.2777851165098011f
#define H6 0.1913417161825449f
#define H7 0.0975451610080641f

__constant__ float Qc[8][8] = {
    { H0,  H0,  H0,  H0,  H0,  H0,  H0,  H0},
    { H1,  H3,  H5,  H7, -H7, -H5, -H3, -H1},
    { H2,  H6, -H6, -H2, -H2, -H6,  H6,  H2},
    { H3, -H7, -H1, -H5,  H5,  H1,  H7, -H3},
    { H4, -H4, -H4,  H4,  H4, -H4, -H4,  H4},
    { H5, -H1,  H7,  H3, -H3, -H7,  H1, -H5},
    { H6, -H2,  H2, -H6, -H6,  H2, -H2,  H6},
    { H7, -H5,  H3, -H1,  H1, -H3,  H5, -H7},
};

__constant__ int ZIGc[64] = {
     0,  1,  8, 16,  9,  2,  3, 10, 17, 24, 32, 25, 18, 11,  4,  5,
    12, 19, 26, 33, 40, 48, 41, 34, 27, 20, 13,  6,  7, 14, 21, 28,
    35, 42, 49, 56, 57, 50, 43, 36, 29, 22, 15, 23, 30, 37, 44, 51,
    58, 59, 52, 45, 38, 31, 39, 46, 53, 60, 61, 54, 47, 55, 62, 63
};

// ---------------------------------------------------------------------------
// Threefry-2x32 (20 rounds) — matches JAX exactly (verified bit-exact)
// ---------------------------------------------------------------------------
__device__ __forceinline__ void tf2(uint32_t k0, uint32_t k1,
                                    uint32_t& x0, uint32_t& x1) {
    const uint32_t ks2 = k0 ^ k1 ^ 0x1BD11BDAu;
    x0 += k0; x1 += k1;
#define TFR(r) { x0 += x1; x1 = (x1 << (r)) | (x1 >> (32 - (r))); x1 ^= x0; }
    TFR(13) TFR(15) TFR(26) TFR(6)   x0 += k1;  x1 += ks2 + 1u;
    TFR(17) TFR(29) TFR(16) TFR(24)  x0 += ks2; x1 += k0  + 2u;
    TFR(13) TFR(15) TFR(26) TFR(6)   x0 += k0;  x1 += k1  + 3u;
    TFR(17) TFR(29) TFR(16) TFR(24)  x0 += k1;  x1 += ks2 + 4u;
    TFR(13) TFR(15) TFR(26) TFR(6)   x0 += ks2; x1 += k0  + 5u;
#undef TFR
}

// ---------------------------------------------------------------------------
// Kernel 1: RGB->Y + 8x8 2D DCT. One thread = one 8x8 block. (48us, 63% DRAM)
// ---------------------------------------------------------------------------
__global__ void __launch_bounds__(256) dct_kernel(const float* __restrict__ x,
                                                  float* __restrict__ out) {
    int g   = blockIdx.x * 256 + threadIdx.x;
    int b   = g >> 12;
    int blk = g & 4095;
    int bi  = blk >> 6;
    int bj  = blk & 63;

    const float* xr = x + (size_t)b * 3 * IMG_PIX;
    const float* xg = xr + IMG_PIX;
    const float* xb = xg + IMG_PIX;
    int base = bi * 8 * HW + bj * 8;

    float T[8][8];
#pragma unroll
    for (int i = 0; i < 8; i++)
#pragma unroll
        for (int jj = 0; jj < 8; jj++) T[i][jj] = 0.0f;

#pragma unroll
    for (int k = 0; k < 8; k++) {
        int off = base + k * HW;
        float4 r0 = __ldg((const float4*)(xr + off));
        float4 r1 = __ldg((const float4*)(xr + off) + 1);
        float4 g0 = __ldg((const float4*)(xg + off));
        float4 g1 = __ldg((const float4*)(xg + off) + 1);
        float4 c0 = __ldg((const float4*)(xb + off));
        float4 c1 = __ldg((const float4*)(xb + off) + 1);

        float y[8];
        y[0] = 0.299f * r0.x + 0.587f * g0.x + 0.114f * c0.x;
        y[1] = 0.299f * r0.y + 0.587f * g0.y + 0.114f * c0.y;
        y[2] = 0.299f * r0.z + 0.587f * g0.z + 0.114f * c0.z;
        y[3] = 0.299f * r0.w + 0.587f * g0.w + 0.114f * c0.w;
        y[4] = 0.299f * r1.x + 0.587f * g1.x + 0.114f * c1.x;
        y[5] = 0.299f * r1.y + 0.587f * g1.y + 0.114f * c1.y;
        y[6] = 0.299f * r1.z + 0.587f * g1.z + 0.114f * c1.z;
        y[7] = 0.299f * r1.w + 0.587f * g1.w + 0.114f * c1.w;

#pragma unroll
        for (int i = 0; i < 8; i++) {
            float q = Qc[i][k];
#pragma unroll
            for (int jj = 0; jj < 8; jj++)
                T[i][jj] = fmaf(q, y[jj], T[i][jj]);
        }
    }

    float* o = out + (size_t)b * IMG_PIX + base;
#pragma unroll
    for (int i = 0; i < 8; i++) {
        float d[8];
#pragma unroll
        for (int l = 0; l < 8; l++) {
            float acc = 0.0f;
#pragma unroll
            for (int k = 0; k < 8; k++)
                acc = fmaf(T[i][k], Qc[l][k], acc);
            d[l] = acc;
        }
        float4* op = (float4*)(o + i * HW);
        op[0] = make_float4(d[0], d[1], d[2], d[3]);
        op[1] = make_float4(d[4], d[5], d[6], d[7]);
    }
}

// exclusive 512-bin scan; all 512 threads must participate (contains syncs)
__device__ __forceinline__ uint32_t scan512(uint32_t h, int lane, int wid,
                                            uint32_t* wsum) {
    uint32_t inc = h;
#pragma unroll
    for (int off = 1; off < 32; off <<= 1) {
        uint32_t nn = __shfl_up_sync(0xFFFFFFFFu, inc, off);
        if (lane >= off) inc += nn;
    }
    if (lane == 31) wsum[wid] = inc;
    __syncthreads();
    if (wid == 0) {
        uint32_t v = (lane < 16) ? wsum[lane] : 0u;
        uint32_t vi = v;
#pragma unroll
        for (int off = 1; off < 16; off <<= 1) {
            uint32_t nn = __shfl_up_sync(0xFFFFFFFFu, vi, off);
            if (lane >= off) vi += nn;
        }
        if (lane < 16) wsum[lane] = vi - v;
    }
    __syncthreads();
    return inc - h + wsum[wid];
}

// ---------------------------------------------------------------------------
// Kernel 2: JAX permutation + fused gather.
//  Phase A: round-2 top-250 via THRESHOLD selection (digit < TCAND candidates
//           only; downward-closed => candidate rank == global rank).
//           posmap[round1_rank]=pos, bitmap of selected ranks.
//  Phase B: round-1 sparse sort — full histogram, bitmap-flagged buckets,
//           compacted scatter, rank over compacted list; winners emit index.
// Composite: (sk << 12) | i  (44-bit, distinct). Digit = bits [35,44).
// ---------------------------------------------------------------------------
__global__ void __launch_bounds__(512, 3) perm_kernel(float* __restrict__ out) {
    extern __shared__ char smem[];
    unsigned long long* arr  = (unsigned long long*)(smem + OFF_ARR);
    unsigned long long* cand = arr;                            // A: [0,1024)
    unsigned long long* scatA = arr + 1024;                    // A: grouped
    unsigned long long* scat = (unsigned long long*)(smem + OFF_SCAT);
    uint32_t* hist   = (uint32_t*)(smem + OFF_HIST);           // + cursor
    uint32_t* starts = (uint32_t*)(smem + OFF_STARTS);
    uint32_t* fst    = (uint32_t*)(smem + OFF_FST);
    uint32_t* wsum   = (uint32_t*)(smem + OFF_WSUM);
    uint32_t* cnt    = (uint32_t*)(smem + OFF_CNT);            // [0]=ncand [1]=nscat
    int*      fidx   = (int*)(smem + OFF_FIDX);
    uint16_t* posmap = (uint16_t*)(smem + OFF_POSMAP);
    uint32_t* bitmap = (uint32_t*)(smem + OFF_BITMAP);
    uint8_t*  flag   = (uint8_t*)(smem + OFF_FLAG);

    const int tid  = threadIdx.x;
    const int lane = tid & 31;
    const int wid  = tid >> 5;
    const int j    = blockIdx.x;

    // keys[j] from top-level split of key(0) = (0,0)
    uint32_t key0 = 0u, key1 = (uint32_t)j;
    tf2(0u, 0u, key0, key1);
    // subkeys: round1 = tf2(key,(0,1)); key2 = tf2(key,(0,0)); round2 = tf2(key2,(0,1))
    uint32_t s0 = 0u, s1 = 1u; tf2(key0, key1, s0, s1);
    uint32_t k20 = 0u, k21 = 0u; tf2(key0, key1, k20, k21);
    uint32_t t0 = 0u, t1 = 1u; tf2(k20, k21, t0, t1);

    // =============== PHASE A: round-2 top-250 (threshold) ==================
    hist[tid] = 0;
    if (tid < 128) bitmap[tid] = 0;
    if (tid == 0) { cnt[0] = 0; cnt[1] = 0; }
    {   // posmap := 0xFFFF
        uint32_t* pm = (uint32_t*)posmap;
        pm[tid] = 0xFFFFFFFFu; pm[tid + 512] = 0xFFFFFFFFu;
        pm[tid + 1024] = 0xFFFFFFFFu; pm[tid + 1536] = 0xFFFFFFFFu;
    }
    __syncthreads();

    for (int q = 0; q < 8; q++) {
        int i = tid + q * 512;
        uint32_t b1 = 0u, b2 = (uint32_t)i;
        tf2(t0, t1, b1, b2);
        uint32_t sk = b1 ^ b2;
        uint32_t d = sk >> 23;
        if (d < TCAND) {
            unsigned long long cc =
                ((unsigned long long)sk << 12) | (unsigned)i;
            uint32_t p = atomicAdd(&cnt[0], 1u);
            if (p < CAPA) cand[p] = cc;
            atomicAdd(&hist[d], 1u);
        }
    }
    __syncthreads();

    {   // scan (bins >= TCAND are zero)
        uint32_t h = hist[tid];
        uint32_t excl = scan512(h, lane, wid, wsum);
        starts[tid] = excl;
        hist[tid]   = excl;      // cursor
    }
    __syncthreads();

    const uint32_t NC = min(cnt[0], CAPA);
    // group candidates by digit
    for (uint32_t t = tid; t < NC; t += 512) {
        unsigned long long cc = cand[t];
        uint32_t d = (uint32_t)(cc >> 35);
        uint32_t p = atomicAdd(&hist[d], 1u);
        scatA[p] = cc;
    }
    __syncthreads();

    // rank candidates; winners: posmap + bitmap
    for (uint32_t t = tid; t < NC; t += 512) {
        unsigned long long cc = scatA[t];
        uint32_t d = (uint32_t)(cc >> 35);
        uint32_t lo = starts[d], hi = starts[d + 1];
        uint32_t r = 0;
        for (uint32_t m = lo; m < hi; m++)
            r += (scatA[m] < cc);
        uint32_t pos = lo + r;
        if (pos < NSAMP) {
            uint32_t slot = (uint32_t)(cc & 0xFFFull);
            posmap[slot] = (uint16_t)pos;
            atomicOr(&bitmap[slot >> 5], 1u << (slot & 31));
        }
    }
    __syncthreads();
    hist[tid] = 0;
    __syncthreads();

    // ==================== PHASE B: round-1 sparse sort ======================
    for (int q = 0; q < 8; q++) {
        int i = tid + q * 512;
        uint32_t b1 = 0u, b2 = (uint32_t)i;
        tf2(s0, s1, b1, b2);
        unsigned long long cc =
            ((unsigned long long)(b1 ^ b2) << 12) | (unsigned)i;
        arr[i] = cc;
        atomicAdd(&hist[(uint32_t)(cc >> 35)], 1u);
    }
    __syncthreads();

    uint32_t hB = hist[tid];
    {
        uint32_t excl = scan512(hB, lane, wid, wsum);
        starts[tid] = excl;
        if (tid == 0) starts[NBIN] = NELEM;
    }
    __syncthreads();

    // flag buckets via bitmap over rank range [lo, hi)
    uint8_t fl = 0;
    {
        uint32_t lo = starts[tid], hi = starts[tid + 1];
        if (hi > lo) {
            uint32_t w0 = lo >> 5, w1 = (hi - 1) >> 5;
            uint32_t f = 0;
            for (uint32_t w = w0; w <= w1; w++) {
                uint32_t m = 0xFFFFFFFFu;
                if (w == w0) m &= 0xFFFFFFFFu << (lo & 31);
                if (w == w1) m &= 0xFFFFFFFFu >> (31 - ((hi - 1) & 31));
                f |= bitmap[w] & m;
            }
            fl = (f != 0);
        }
        flag[tid] = fl;
    }
    __syncthreads();

    // compacted scan over flagged buckets
    {
        uint32_t fh = fl ? hB : 0u;
        uint32_t fexcl = scan512(fh, lane, wid, wsum);
        fst[tid]  = fexcl;
        hist[tid] = fexcl;       // cursor
        if (tid == 511) cnt[1] = fexcl + fh;
    }
    __syncthreads();

    // scatter flagged-bucket elements (compacted)
    for (int q = 0; q < 8; q++) {
        unsigned long long cc = arr[tid + q * 512];
        uint32_t d = (uint32_t)(cc >> 35);
        if (flag[d]) {
            uint32_t p = atomicAdd(&hist[d], 1u);
            if (p < SCATN) scat[p] = cc;
        }
    }
    __syncthreads();

    // rank compacted elements; winners emit block index
    const uint32_t NS = min(cnt[1], (uint32_t)SCATN);
    for (uint32_t t = tid; t < NS; t += 512) {
        unsigned long long cc = scat[t];
        uint32_t d = (uint32_t)(cc >> 35);
        uint32_t flo = fst[d];
        uint32_t bsz = starts[d + 1] - starts[d];
        uint32_t r = 0;
        for (uint32_t m = flo; m < flo + bsz; m++)
            r += (scat[m] < cc);
        uint32_t fp = starts[d] + r;          // global round-1 rank
        uint16_t p = posmap[fp];
        if (p != 0xFFFFu)
            fidx[p] = (int)(cc & 0xFFFull);
    }
    __syncthreads();

    // ========================= fused sample gather =========================
    if (tid < NSAMP) {
        int b = j >> 6;
        int z = j & 63;
        int blk = fidx[tid];
        int loc = ZIGc[z];
        int u = loc >> 3, v = loc & 7;
        int bi = blk >> 6, bj = blk & 63;
        float val = out[(size_t)b * IMG_PIX +
                        (size_t)(bi * 8 + u) * HW + bj * 8 + v];
        out[(size_t)IMG_ELEMS + (size_t)j * NSAMP + tid] = val;
    }
}

// ---------------------------------------------------------------------------
extern "C" void kernel_launch(void* const* d_in, const int* in_sizes, int n_in,
                              void* d_out, int out_size) {
    (void)in_sizes; (void)n_in; (void)out_size;
    const float* x = (const float*)d_in[0];
    float* out = (float*)d_out;

    cudaFuncSetAttribute(perm_kernel,
                         cudaFuncAttributeMaxDynamicSharedMemorySize,
                         SMEM_BYTES);

    dct_kernel<<<1024, 256>>>(x, out);
    perm_kernel<<<NPERM, 512, SMEM_BYTES>>>(out);
}